// round 2
// baseline (speedup 1.0000x reference)
#include <cuda_runtime.h>
#include <math.h>

#define BATCH     2000000
#define LAM       0.1
#define NBLOCKS   1184      // 148 SMs * 8
#define NTHREADS  256

// Per-block partials: [b][0]=bce, [b][1]=sum(u*u), [b][2]=sum(v*v).
// Written unconditionally every launch -> no zero-init kernel needed.
__device__ double g_part[NBLOCKS][3];
// Zero-initialized at module load; the LAST block resets it to 0 each launch,
// so every graph replay sees the same initial state (deterministic).
__device__ unsigned int g_ticket;

__device__ __forceinline__ double warp_reduce_d(double v) {
    #pragma unroll
    for (int o = 16; o > 0; o >>= 1)
        v += __shfl_down_sync(0xffffffffu, v, o);
    return v;
}

__global__ void __launch_bounds__(NTHREADS) pmf_fused_kernel(
    const int*    __restrict__ user,
    const int*    __restrict__ item,
    const float*  __restrict__ ratings,
    const float4* __restrict__ ue,   // user_embedding rows as 8x float4
    const float4* __restrict__ ve,   // item_embedding rows as 8x float4
    float*        __restrict__ out)
{
    const int lane = threadIdx.x & 31;
    const int sub  = lane & 7;   // dim-chunk within 8-lane group
    const int grp  = lane >> 3;  // interaction-within-quad 0..3

    const int warp_id = (blockIdx.x * NTHREADS + threadIdx.x) >> 5;
    const int nwarps  = (NBLOCKS * NTHREADS) >> 5;

    float bce = 0.0f, uu = 0.0f, vv = 0.0f;

    const int nchunks = BATCH / 32;   // 62500 warp-chunks of 32 interactions
    for (int c = warp_id; c < nchunks; c += nwarps) {
        const int base = c * 32;
        const int   uidx = user[base + lane];
        const int   iidx = item[base + lane];
        const float rat  = ratings[base + lane];

        #pragma unroll
        for (int j = 0; j < 8; j++) {
            const int src = j * 4 + grp;
            const int   ui = __shfl_sync(0xffffffffu, uidx, src);
            const int   ii = __shfl_sync(0xffffffffu, iidx, src);
            const float r  = __shfl_sync(0xffffffffu, rat,  src);

            // 8 lanes x float4 = 128B = exactly one embedding row / L2 line
            const float4 u = ue[ui * 8 + sub];
            const float4 v = ve[ii * 8 + sub];

            uu += u.x*u.x + u.y*u.y + u.z*u.z + u.w*u.w;
            vv += v.x*v.x + v.y*v.y + v.z*v.z + v.w*v.w;

            float p = u.x*v.x + u.y*v.y + u.z*v.z + u.w*v.w;
            p += __shfl_xor_sync(0xffffffffu, p, 4);
            p += __shfl_xor_sync(0xffffffffu, p, 2);
            p += __shfl_xor_sync(0xffffffffu, p, 1);

            if (sub == 0) {
                // stable BCE-with-logits: max(p,0) - p*r + log1p(exp(-|p|))
                bce += fmaxf(p, 0.0f) - p * r + log1pf(__expf(-fabsf(p)));
            }
        }
    }

    // ---- block reduction (double) ----
    __shared__ double s_b[8], s_u[8], s_v[8];
    __shared__ bool   s_last;
    const int wib = threadIdx.x >> 5;

    double db = warp_reduce_d((double)bce);
    double du = warp_reduce_d((double)uu);
    double dv = warp_reduce_d((double)vv);
    if (lane == 0) { s_b[wib] = db; s_u[wib] = du; s_v[wib] = dv; }
    __syncthreads();

    if (threadIdx.x == 0) {
        double b2 = 0.0, u2 = 0.0, v2 = 0.0;
        #pragma unroll
        for (int i = 0; i < NTHREADS / 32; i++) { b2 += s_b[i]; u2 += s_u[i]; v2 += s_v[i]; }
        g_part[blockIdx.x][0] = b2;
        g_part[blockIdx.x][1] = u2;
        g_part[blockIdx.x][2] = v2;
        __threadfence();
        unsigned int t = atomicAdd(&g_ticket, 1u);
        bool last = (t == NBLOCKS - 1);
        if (last) g_ticket = 0;   // reset for next graph replay
        s_last = last;
    }
    __syncthreads();

    // ---- last block finalizes ----
    if (s_last) {
        __threadfence();  // acquire all blocks' partials
        double b = 0.0, u = 0.0, v = 0.0;
        for (int i = threadIdx.x; i < NBLOCKS; i += NTHREADS) {
            b += g_part[i][0];
            u += g_part[i][1];
            v += g_part[i][2];
        }
        b = warp_reduce_d(b);
        u = warp_reduce_d(u);
        v = warp_reduce_d(v);
        if (lane == 0) { s_b[wib] = b; s_u[wib] = u; s_v[wib] = v; }
        __syncthreads();
        if (threadIdx.x == 0) {
            double fb = 0.0, fu = 0.0, fv = 0.0;
            #pragma unroll
            for (int i = 0; i < NTHREADS / 32; i++) { fb += s_b[i]; fu += s_u[i]; fv += s_v[i]; }
            out[0] = (float)(fb + LAM * sqrt(fu) + LAM * sqrt(fv));
        }
    }
}

extern "C" void kernel_launch(void* const* d_in, const int* in_sizes, int n_in,
                              void* d_out, int out_size) {
    const int*    user = (const int*)d_in[0];
    const int*    item = (const int*)d_in[1];
    const float*  rat  = (const float*)d_in[2];
    const float4* ue   = (const float4*)d_in[3];
    const float4* ve   = (const float4*)d_in[4];
    float* out = (float*)d_out;

    pmf_fused_kernel<<<NBLOCKS, NTHREADS>>>(user, item, rat, ue, ve, out);
}

// round 3
// speedup vs baseline: 1.0331x; 1.0331x over previous
#include <cuda_runtime.h>
#include <math.h>

#define BATCH     2000000
#define LAM       0.1
#define NBLOCKS   1184      // 148 SMs * 8
#define NTHREADS  256

__device__ double g_part[NBLOCKS][3];
__device__ unsigned int g_ticket;   // zero-init; last block resets -> graph-replay safe

// ---- Blackwell packed f32x2 helpers ----
__device__ __forceinline__ unsigned long long f2mul(unsigned long long a, unsigned long long b) {
    unsigned long long d;
    asm("mul.rn.f32x2 %0, %1, %2;" : "=l"(d) : "l"(a), "l"(b));
    return d;
}
__device__ __forceinline__ unsigned long long f2fma(unsigned long long a, unsigned long long b, unsigned long long c) {
    unsigned long long d;
    asm("fma.rn.f32x2 %0, %1, %2, %3;" : "=l"(d) : "l"(a), "l"(b), "l"(c));
    return d;
}
__device__ __forceinline__ float f2sum(unsigned long long a) {
    float lo, hi;
    asm("mov.b64 {%0,%1}, %2;" : "=f"(lo), "=f"(hi) : "l"(a));
    return lo + hi;
}

__device__ __forceinline__ double warp_reduce_d(double v) {
    #pragma unroll
    for (int o = 16; o > 0; o >>= 1)
        v += __shfl_down_sync(0xffffffffu, v, o);
    return v;
}

__global__ void __launch_bounds__(NTHREADS) pmf_fused_kernel(
    const int*        __restrict__ user,
    const int*        __restrict__ item,
    const float*      __restrict__ ratings,
    const ulonglong2* __restrict__ ue,   // row = 8x ulonglong2, each half = f32x2
    const ulonglong2* __restrict__ ve,
    float*            __restrict__ out)
{
    const int lane = threadIdx.x & 31;
    const int sub  = lane & 7;   // dim-chunk within 8-lane group; also "my" j
    const int grp  = lane >> 3;  // interaction-within-quad 0..3

    const int warp_id = (blockIdx.x * NTHREADS + threadIdx.x) >> 5;
    const int nwarps  = (NBLOCKS * NTHREADS) >> 5;

    // interaction (within a 32-chunk) this lane is responsible for BCE-ing:
    const int my_src = (sub << 2) | grp;   // = 4*sub + grp

    float bce = 0.0f;
    unsigned long long uu2 = 0ull, vv2 = 0ull;  // packed f32x2 accumulators

    const int nchunks = BATCH / 32;
    for (int c = warp_id; c < nchunks; c += nwarps) {
        const int base = c * 32;
        const int   uidx = user[base + lane];
        const int   iidx = item[base + lane];
        // each lane fetches exactly the rating of the interaction it will BCE
        const float myr = __shfl_sync(0xffffffffu,
                                      ratings[base + lane], my_src);

        float mylogit = 0.0f;

        #pragma unroll
        for (int j = 0; j < 8; j++) {
            const int src = j * 4 + grp;
            const int ui = __shfl_sync(0xffffffffu, uidx, src);
            const int ii = __shfl_sync(0xffffffffu, iidx, src);

            // 8 lanes x 16B = 128B = one embedding row = one L2 line
            const ulonglong2 u = ue[ui * 8 + sub];
            const ulonglong2 v = ve[ii * 8 + sub];

            uu2 = f2fma(u.x, u.x, uu2);
            uu2 = f2fma(u.y, u.y, uu2);
            vv2 = f2fma(v.x, v.x, vv2);
            vv2 = f2fma(v.y, v.y, vv2);

            unsigned long long d2 = f2mul(u.x, v.x);
            d2 = f2fma(u.y, v.y, d2);
            float p = f2sum(d2);
            // reduce within 8-lane group -> every lane holds the group's logit
            p += __shfl_xor_sync(0xffffffffu, p, 4);
            p += __shfl_xor_sync(0xffffffffu, p, 2);
            p += __shfl_xor_sync(0xffffffffu, p, 1);

            if (sub == j) mylogit = p;   // bijective lane<->interaction keep
        }

        // one BCE per lane per chunk, all 32 lanes active
        // stable: max(x,0) - x*r + log(1 + exp(-|x|))
        const float x = mylogit;
        bce += fmaxf(x, 0.0f) - x * myr + __logf(1.0f + __expf(-fabsf(x)));
    }

    const float uu = f2sum(uu2);
    const float vv = f2sum(vv2);

    // ---- block reduction (double) ----
    __shared__ double s_b[8], s_u[8], s_v[8];
    __shared__ bool   s_last;
    const int wib = threadIdx.x >> 5;

    double db = warp_reduce_d((double)bce);
    double du = warp_reduce_d((double)uu);
    double dv = warp_reduce_d((double)vv);
    if (lane == 0) { s_b[wib] = db; s_u[wib] = du; s_v[wib] = dv; }
    __syncthreads();

    if (threadIdx.x == 0) {
        double b2 = 0.0, u2 = 0.0, v2 = 0.0;
        #pragma unroll
        for (int i = 0; i < NTHREADS / 32; i++) { b2 += s_b[i]; u2 += s_u[i]; v2 += s_v[i]; }
        g_part[blockIdx.x][0] = b2;
        g_part[blockIdx.x][1] = u2;
        g_part[blockIdx.x][2] = v2;
        __threadfence();
        unsigned int t = atomicAdd(&g_ticket, 1u);
        bool last = (t == NBLOCKS - 1);
        if (last) g_ticket = 0;
        s_last = last;
    }
    __syncthreads();

    if (s_last) {
        __threadfence();
        double b = 0.0, u = 0.0, v = 0.0;
        for (int i = threadIdx.x; i < NBLOCKS; i += NTHREADS) {
            b += g_part[i][0];
            u += g_part[i][1];
            v += g_part[i][2];
        }
        b = warp_reduce_d(b);
        u = warp_reduce_d(u);
        v = warp_reduce_d(v);
        if (lane == 0) { s_b[wib] = b; s_u[wib] = u; s_v[wib] = v; }
        __syncthreads();
        if (threadIdx.x == 0) {
            double fb = 0.0, fu = 0.0, fv = 0.0;
            #pragma unroll
            for (int i = 0; i < NTHREADS / 32; i++) { fb += s_b[i]; fu += s_u[i]; fv += s_v[i]; }
            out[0] = (float)(fb + LAM * sqrt(fu) + LAM * sqrt(fv));
        }
    }
}

extern "C" void kernel_launch(void* const* d_in, const int* in_sizes, int n_in,
                              void* d_out, int out_size) {
    const int*        user = (const int*)d_in[0];
    const int*        item = (const int*)d_in[1];
    const float*      rat  = (const float*)d_in[2];
    const ulonglong2* ue   = (const ulonglong2*)d_in[3];
    const ulonglong2* ve   = (const ulonglong2*)d_in[4];
    float* out = (float*)d_out;

    pmf_fused_kernel<<<NBLOCKS, NTHREADS>>>(user, item, rat, ue, ve, out);
}

// round 4
// speedup vs baseline: 1.2089x; 1.1702x over previous
#include <cuda_runtime.h>
#include <math.h>

#define BATCH     2000000
#define LAM       0.1
#define NBLOCKS   1184      // 148 SMs * 8
#define NTHREADS  256
#define NWARPS    ((NBLOCKS * NTHREADS) >> 5)
#define NCHUNKS   (BATCH / 32)

__device__ double g_part[NBLOCKS][3];
__device__ unsigned int g_ticket;   // zero-init; last block resets -> graph-replay safe

__device__ __forceinline__ double warp_reduce_d(double v) {
    #pragma unroll
    for (int o = 16; o > 0; o >>= 1)
        v += __shfl_down_sync(0xffffffffu, v, o);
    return v;
}

__global__ void __launch_bounds__(NTHREADS, 8) pmf_fused_kernel(
    const int*    __restrict__ user,
    const int*    __restrict__ item,
    const float*  __restrict__ ratings,
    const float4* __restrict__ ue,   // embedding row = 8 x float4 = one 128B line
    const float4* __restrict__ ve,
    float*        __restrict__ out)
{
    const int lane = threadIdx.x & 31;
    const int sub  = lane & 7;   // dim-chunk within 8-lane group; also "my" j
    const int grp  = lane >> 3;  // interaction-within-quad 0..3

    const int warp_id = (blockIdx.x * NTHREADS + threadIdx.x) >> 5;
    const int my_src  = (sub << 2) | grp;  // interaction this lane BCEs

    float bce = 0.0f, uu = 0.0f, vv = 0.0f;

    // software pipeline: preload chunk c's indices before processing
    int c = warp_id;
    int   uidx = 0, iidx = 0;
    float rat  = 0.0f;
    if (c < NCHUNKS) {
        uidx = user[c * 32 + lane];
        iidx = item[c * 32 + lane];
        rat  = ratings[c * 32 + lane];
    }

    for (; c < NCHUNKS; ) {
        const int   cu = uidx;
        const int   ci = iidx;
        const float cr = rat;

        // prefetch next chunk's coalesced streams (overlaps the gather phase)
        const int cn = c + NWARPS;
        if (cn < NCHUNKS) {
            uidx = user[cn * 32 + lane];
            iidx = item[cn * 32 + lane];
            rat  = ratings[cn * 32 + lane];
        }

        const float myr = __shfl_sync(0xffffffffu, cr, my_src);

        float mylogit = 0.0f;

        #pragma unroll
        for (int j = 0; j < 8; j++) {
            const int src = j * 4 + grp;
            const int ui = __shfl_sync(0xffffffffu, cu, src);
            const int ii = __shfl_sync(0xffffffffu, ci, src);

            // 8 lanes x float4 = 128B = one embedding row = one L2 line
            const float4 u = ue[ui * 8 + sub];
            const float4 v = ve[ii * 8 + sub];

            uu += u.x*u.x + u.y*u.y + u.z*u.z + u.w*u.w;
            vv += v.x*v.x + v.y*v.y + v.z*v.z + v.w*v.w;

            float p = u.x*v.x + u.y*v.y + u.z*v.z + u.w*v.w;
            p += __shfl_xor_sync(0xffffffffu, p, 4);
            p += __shfl_xor_sync(0xffffffffu, p, 2);
            p += __shfl_xor_sync(0xffffffffu, p, 1);

            if (sub == j) mylogit = p;   // bijective lane<->interaction keep
        }

        // one BCE per lane per chunk, all lanes active:
        // max(x,0) - x*r + log(1 + exp(-|x|))   (logits ~±0.05 -> __logf safe)
        const float x = mylogit;
        bce += fmaxf(x, 0.0f) - x * myr + __logf(1.0f + __expf(-fabsf(x)));

        c = cn;
    }

    // ---- block reduction (double) ----
    __shared__ double s_b[8], s_u[8], s_v[8];
    __shared__ bool   s_last;
    const int wib = threadIdx.x >> 5;

    double db = warp_reduce_d((double)bce);
    double du = warp_reduce_d((double)uu);
    double dv = warp_reduce_d((double)vv);
    if (lane == 0) { s_b[wib] = db; s_u[wib] = du; s_v[wib] = dv; }
    __syncthreads();

    if (threadIdx.x == 0) {
        double b2 = 0.0, u2 = 0.0, v2 = 0.0;
        #pragma unroll
        for (int i = 0; i < NTHREADS / 32; i++) { b2 += s_b[i]; u2 += s_u[i]; v2 += s_v[i]; }
        g_part[blockIdx.x][0] = b2;
        g_part[blockIdx.x][1] = u2;
        g_part[blockIdx.x][2] = v2;
        __threadfence();
        unsigned int t = atomicAdd(&g_ticket, 1u);
        bool last = (t == NBLOCKS - 1);
        if (last) g_ticket = 0;
        s_last = last;
    }
    __syncthreads();

    if (s_last) {
        __threadfence();
        double b = 0.0, u = 0.0, v = 0.0;
        for (int i = threadIdx.x; i < NBLOCKS; i += NTHREADS) {
            b += g_part[i][0];
            u += g_part[i][1];
            v += g_part[i][2];
        }
        b = warp_reduce_d(b);
        u = warp_reduce_d(u);
        v = warp_reduce_d(v);
        if (lane == 0) { s_b[wib] = b; s_u[wib] = u; s_v[wib] = v; }
        __syncthreads();
        if (threadIdx.x == 0) {
            double fb = 0.0, fu = 0.0, fv = 0.0;
            #pragma unroll
            for (int i = 0; i < NTHREADS / 32; i++) { fb += s_b[i]; fu += s_u[i]; fv += s_v[i]; }
            out[0] = (float)(fb + LAM * sqrt(fu) + LAM * sqrt(fv));
        }
    }
}

extern "C" void kernel_launch(void* const* d_in, const int* in_sizes, int n_in,
                              void* d_out, int out_size) {
    const int*    user = (const int*)d_in[0];
    const int*    item = (const int*)d_in[1];
    const float*  rat  = (const float*)d_in[2];
    const float4* ue   = (const float4*)d_in[3];
    const float4* ve   = (const float4*)d_in[4];
    float* out = (float*)d_out;

    pmf_fused_kernel<<<NBLOCKS, NTHREADS>>>(user, item, rat, ue, ve, out);
}